// round 3
// baseline (speedup 1.0000x reference)
#include <cuda_runtime.h>
#include <cstdint>
#include <cstddef>

// Problem constants (shapes fixed by the dataset)
#define NNODES 50000
#define NEDGES 800000
#define NCOLS  512
#define NGRAPH 64

// ---------------------------------------------------------------------------
// Scratch (device globals; no allocation allowed)
// ---------------------------------------------------------------------------
__device__ float g_agg[(size_t)NNODES * NCOLS];     // neighbor aggregate
__device__ float g_z[(size_t)NNODES * NCOLS];       // pre-BN linear output
__device__ float g_h1[(size_t)NNODES * NCOLS];      // layer-1 output
__device__ float g_stats[2 * NCOLS];                // per-col sum / sumsq
__device__ float g_scale[NCOLS];                    // BN fused scale
__device__ float g_shift[NCOLS];                    // BN fused shift
__device__ float g_pooled[(size_t)NGRAPH * NCOLS];  // graph pooling
__device__ int   g_src[NEDGES];                     // canonical int32 indices
__device__ int   g_dst[NEDGES];
__device__ int   g_batch[NNODES];
__device__ int   g_is64;                            // index dtype flag

// ---------------------------------------------------------------------------
// Index dtype detection + canonicalization (int32 vs int64 input)
// For int64 (values < 2^31, little-endian) every odd 32-bit word is 0.
// ---------------------------------------------------------------------------
__global__ void detect_kernel(const unsigned* __restrict__ ei_words)
{
    // 128 threads sample odd words 1,3,...,255
    unsigned v = ei_words[2 * threadIdx.x + 1];
    unsigned any = __ballot_sync(0xffffffffu, v != 0u);
    __shared__ int s_any;
    if (threadIdx.x == 0) s_any = 0;
    __syncthreads();
    if ((threadIdx.x & 31) == 0 && any) atomicOr(&s_any, 1);
    __syncthreads();
    if (threadIdx.x == 0) g_is64 = (s_any == 0) ? 1 : 0;
}

__global__ void convert_kernel(const void* __restrict__ ei,
                               const void* __restrict__ batch,
                               int E, int N)
{
    int i = blockIdx.x * blockDim.x + threadIdx.x;
    int is64 = g_is64;
    if (i < E) {
        if (is64) {
            g_src[i] = (int)((const long long*)ei)[i];
            g_dst[i] = (int)((const long long*)ei)[E + i];
        } else {
            g_src[i] = ((const int*)ei)[i];
            g_dst[i] = ((const int*)ei)[E + i];
        }
    }
    if (i < N) {
        g_batch[i] = is64 ? (int)((const long long*)batch)[i]
                          : ((const int*)batch)[i];
    }
}

// ---------------------------------------------------------------------------
// Vectorized global reduction (sm_90+): 4 floats per RED op
// ---------------------------------------------------------------------------
__device__ __forceinline__ void red_add_v4(float* addr, float4 v) {
    asm volatile("red.global.add.v4.f32 [%0], {%1, %2, %3, %4};"
                 :: "l"(addr), "f"(v.x), "f"(v.y), "f"(v.z), "f"(v.w)
                 : "memory");
}

// ---------------------------------------------------------------------------
// Edge scatter: agg[dst] += feat[src].  One warp per edge, float4 lanes.
// ---------------------------------------------------------------------------
__global__ void scatter_kernel(const float* __restrict__ feat,
                               const int* __restrict__ src,
                               const int* __restrict__ dst,
                               float* __restrict__ agg,
                               int E, int W4)
{
    int warp = (blockIdx.x * blockDim.x + threadIdx.x) >> 5;
    int lane = threadIdx.x & 31;
    if (warp >= E) return;
    int s = src[warp];
    int d = dst[warp];
    const float4* xs = reinterpret_cast<const float4*>(feat) + (size_t)s * W4;
    float*        ad = agg + (size_t)d * (W4 * 4);
    for (int c = lane; c < W4; c += 32) {
        float4 v = xs[c];
        red_add_v4(ad + c * 4, v);
    }
}

// ---------------------------------------------------------------------------
// Fused GEMM:  C[M,512] = Apre[M,K] @ B[K,512] (+bias) (+epilogue)
//   AM==0 : Apre = A0 + A1                         (x + agg)
//   AM==1 : Apre = relu(A0 * scale[k] + shift[k])  (BN+ReLU on z)
//   EM==0 : store C = z+bias; accumulate column sum/sumsq into stats
//   EM==1 : store C = relu(z+bias)
//   EM==2 : red-add relu(z+bias) into pooled[batch[m]]
// Classic 128x128x8 SIMT tile, 256 threads, 8x8 per thread.
// ---------------------------------------------------------------------------
#define BM 128
#define BN 128
#define BK 8
#define TM 8
#define TN 8

template<int AM, int EM>
__global__ void __launch_bounds__(256)
gemm_fused(int M, int K,
           const float* __restrict__ A0, const float* __restrict__ A1,
           const float* __restrict__ scale, const float* __restrict__ shift,
           const float* __restrict__ B, const float* __restrict__ bias,
           float* __restrict__ C, float* __restrict__ stats,
           float* __restrict__ pooled, const int* __restrict__ batch)
{
    __shared__ float As[BK][BM];
    __shared__ float Bs[BK][BN];
    __shared__ float s_sum[BN];
    __shared__ float s_sq[BN];

    const int tid  = threadIdx.x;
    const int row0 = blockIdx.x * BM;
    const int col0 = blockIdx.y * BN;

    const int innerRowA = tid >> 1;          // 0..127
    const int innerColA = (tid & 1) * 4;     // 0 or 4
    const int innerRowB = tid >> 5;          // 0..7
    const int innerColB = (tid & 31) * 4;    // 0..124
    const int tr = tid >> 4;                 // 0..15
    const int tc = tid & 15;                 // 0..15

    if (EM == 0 && tid < BN) { s_sum[tid] = 0.f; s_sq[tid] = 0.f; }

    float acc[TM][TN];
    #pragma unroll
    for (int i = 0; i < TM; i++)
        #pragma unroll
        for (int j = 0; j < TN; j++) acc[i][j] = 0.f;

    for (int k0 = 0; k0 < K; k0 += BK) {
        // ---- load A tile (with fused pre-op) ----
        int gr = row0 + innerRowA;
        float4 av = make_float4(0.f, 0.f, 0.f, 0.f);
        if (gr < M) {
            size_t off = (size_t)gr * K + k0 + innerColA;
            av = *reinterpret_cast<const float4*>(A0 + off);
            if (AM == 0) {
                float4 bv = *reinterpret_cast<const float4*>(A1 + off);
                av.x += bv.x; av.y += bv.y; av.z += bv.z; av.w += bv.w;
            } else {
                float4 sc = *reinterpret_cast<const float4*>(scale + k0 + innerColA);
                float4 sh = *reinterpret_cast<const float4*>(shift + k0 + innerColA);
                av.x = fmaxf(fmaf(av.x, sc.x, sh.x), 0.f);
                av.y = fmaxf(fmaf(av.y, sc.y, sh.y), 0.f);
                av.z = fmaxf(fmaf(av.z, sc.z, sh.z), 0.f);
                av.w = fmaxf(fmaf(av.w, sc.w, sh.w), 0.f);
            }
        }
        As[innerColA + 0][innerRowA] = av.x;
        As[innerColA + 1][innerRowA] = av.y;
        As[innerColA + 2][innerRowA] = av.z;
        As[innerColA + 3][innerRowA] = av.w;

        // ---- load B tile ----
        *reinterpret_cast<float4*>(&Bs[innerRowB][innerColB]) =
            *reinterpret_cast<const float4*>(
                B + (size_t)(k0 + innerRowB) * NCOLS + col0 + innerColB);

        __syncthreads();

        #pragma unroll
        for (int kk = 0; kk < BK; kk++) {
            float ar[TM], br[TN];
            #pragma unroll
            for (int i = 0; i < TM; i++) ar[i] = As[kk][tr * TM + i];
            #pragma unroll
            for (int j = 0; j < TN; j++) br[j] = Bs[kk][tc * TN + j];
            #pragma unroll
            for (int i = 0; i < TM; i++)
                #pragma unroll
                for (int j = 0; j < TN; j++)
                    acc[i][j] = fmaf(ar[i], br[j], acc[i][j]);
        }
        __syncthreads();
    }

    // ---- epilogue ----
    float bcol[TN];
    #pragma unroll
    for (int j = 0; j < TN; j++) bcol[j] = bias[col0 + tc * TN + j];

    if (EM == 0) {
        float psum[TN], psq[TN];
        #pragma unroll
        for (int j = 0; j < TN; j++) { psum[j] = 0.f; psq[j] = 0.f; }
        #pragma unroll
        for (int i = 0; i < TM; i++) {
            int gm = row0 + tr * TM + i;
            if (gm < M) {
                float v[TN];
                #pragma unroll
                for (int j = 0; j < TN; j++) {
                    v[j] = acc[i][j] + bcol[j];
                    psum[j] += v[j];
                    psq[j]  += v[j] * v[j];
                }
                float4* cp = reinterpret_cast<float4*>(
                    C + (size_t)gm * NCOLS + col0 + tc * TN);
                cp[0] = make_float4(v[0], v[1], v[2], v[3]);
                cp[1] = make_float4(v[4], v[5], v[6], v[7]);
            }
        }
        #pragma unroll
        for (int j = 0; j < TN; j++) {
            atomicAdd(&s_sum[tc * TN + j], psum[j]);
            atomicAdd(&s_sq [tc * TN + j], psq [j]);
        }
        __syncthreads();
        if (tid < BN) {
            atomicAdd(&stats[col0 + tid],          s_sum[tid]);
            atomicAdd(&stats[NCOLS + col0 + tid],  s_sq[tid]);
        }
    } else if (EM == 1) {
        #pragma unroll
        for (int i = 0; i < TM; i++) {
            int gm = row0 + tr * TM + i;
            if (gm < M) {
                float v[TN];
                #pragma unroll
                for (int j = 0; j < TN; j++)
                    v[j] = fmaxf(acc[i][j] + bcol[j], 0.f);
                float4* cp = reinterpret_cast<float4*>(
                    C + (size_t)gm * NCOLS + col0 + tc * TN);
                cp[0] = make_float4(v[0], v[1], v[2], v[3]);
                cp[1] = make_float4(v[4], v[5], v[6], v[7]);
            }
        }
    } else {
        #pragma unroll
        for (int i = 0; i < TM; i++) {
            int gm = row0 + tr * TM + i;
            if (gm < M) {
                int b = batch[gm];
                float* p = pooled + (size_t)b * NCOLS + col0 + tc * TN;
                float v[TN];
                #pragma unroll
                for (int j = 0; j < TN; j++)
                    v[j] = fmaxf(acc[i][j] + bcol[j], 0.f);
                red_add_v4(p,     make_float4(v[0], v[1], v[2], v[3]));
                red_add_v4(p + 4, make_float4(v[4], v[5], v[6], v[7]));
            }
        }
    }
}

// ---------------------------------------------------------------------------
// BN stats -> fused scale/shift
// ---------------------------------------------------------------------------
__global__ void bn_finalize(const float* __restrict__ stats,
                            const float* __restrict__ gamma,
                            const float* __restrict__ beta,
                            float* __restrict__ scale,
                            float* __restrict__ shift,
                            float invN)
{
    int c = threadIdx.x;
    float mean = stats[c] * invN;
    float var  = stats[NCOLS + c] * invN - mean * mean;
    float s = gamma[c] * rsqrtf(var + 1e-5f);
    scale[c] = s;
    shift[c] = beta[c] - mean * s;
}

// ---------------------------------------------------------------------------
// Head MLP: out = relu(pooled @ Wl1 + bl1) @ Wl2 + bl2   (64 x 10)
// One block per graph.
// ---------------------------------------------------------------------------
__global__ void head_kernel(const float* __restrict__ pooled,
                            const float* __restrict__ Wl1,
                            const float* __restrict__ bl1,
                            const float* __restrict__ Wl2,
                            const float* __restrict__ bl2,
                            float* __restrict__ out, int OUTC)
{
    __shared__ float sp[NCOLS];
    __shared__ float sh[NCOLS];
    int g = blockIdx.x, t = threadIdx.x;
    sp[t] = pooled[(size_t)g * NCOLS + t];
    __syncthreads();
    float a = bl1[t];
    for (int k = 0; k < NCOLS; k++)
        a = fmaf(sp[k], Wl1[(size_t)k * NCOLS + t], a);
    sh[t] = fmaxf(a, 0.f);
    __syncthreads();
    if (t < 32 * OUTC) {
        int w = t >> 5, l = t & 31;
        float s = 0.f;
        for (int k = l; k < NCOLS; k += 32)
            s = fmaf(sh[k], Wl2[(size_t)k * OUTC + w], s);
        #pragma unroll
        for (int o = 16; o; o >>= 1)
            s += __shfl_down_sync(0xffffffffu, s, o);
        if (l == 0) out[(size_t)g * OUTC + w] = s + bl2[w];
    }
}

// ---------------------------------------------------------------------------
// Launch
// ---------------------------------------------------------------------------
extern "C" void kernel_launch(void* const* d_in, const int* in_sizes, int n_in,
                              void* d_out, int out_size)
{
    const float* x     = (const float*)d_in[0];
    const void*  ei    = d_in[1];
    const void*  batch = d_in[2];
    const float* W1a = (const float*)d_in[3];
    const float* b1a = (const float*)d_in[4];
    const float* g1  = (const float*)d_in[5];
    const float* be1 = (const float*)d_in[6];
    const float* W1b = (const float*)d_in[7];
    const float* b1b = (const float*)d_in[8];
    const float* W2a = (const float*)d_in[9];
    const float* b2a = (const float*)d_in[10];
    const float* g2  = (const float*)d_in[11];
    const float* be2 = (const float*)d_in[12];
    const float* W2b = (const float*)d_in[13];
    const float* b2b = (const float*)d_in[14];
    const float* Wl1 = (const float*)d_in[15];
    const float* bl1 = (const float*)d_in[16];
    const float* Wl2 = (const float*)d_in[17];
    const float* bl2 = (const float*)d_in[18];
    float* out = (float*)d_out;

    const int IN   = 128;
    const int N    = in_sizes[0] / IN;        // 50000
    const int E    = in_sizes[1] / 2;         // 800000
    const int OUTC = in_sizes[18];            // 10
    const int G    = out_size / OUTC;         // 64

    float *agg, *z, *h1, *stats, *scale, *shift, *pooled;
    int *srcI, *dstI, *batchI;
    cudaGetSymbolAddress((void**)&agg,    g_agg);
    cudaGetSymbolAddress((void**)&z,      g_z);
    cudaGetSymbolAddress((void**)&h1,     g_h1);
    cudaGetSymbolAddress((void**)&stats,  g_stats);
    cudaGetSymbolAddress((void**)&scale,  g_scale);
    cudaGetSymbolAddress((void**)&shift,  g_shift);
    cudaGetSymbolAddress((void**)&pooled, g_pooled);
    cudaGetSymbolAddress((void**)&srcI,   g_src);
    cudaGetSymbolAddress((void**)&dstI,   g_dst);
    cudaGetSymbolAddress((void**)&batchI, g_batch);

    // ---- canonicalize indices (int32 vs int64 input) ----
    detect_kernel<<<1, 128>>>((const unsigned*)ei);
    convert_kernel<<<(E + 255) / 256, 256>>>(ei, batch, E, N);

    dim3 ggrid((N + BM - 1) / BM, NCOLS / BN);
    int scatterBlocks = (E + 7) / 8;   // 8 warps per 256-thread block

    // ---------------- Layer 1 ----------------
    cudaMemsetAsync(agg,   0, (size_t)N * IN * sizeof(float));
    cudaMemsetAsync(stats, 0, 2 * NCOLS * sizeof(float));
    scatter_kernel<<<scatterBlocks, 256>>>(x, srcI, dstI, agg, E, IN / 4);
    gemm_fused<0, 0><<<ggrid, 256>>>(N, IN, x, agg, nullptr, nullptr,
                                     W1a, b1a, z, stats, nullptr, nullptr);
    bn_finalize<<<1, NCOLS>>>(stats, g1, be1, scale, shift, 1.0f / N);
    gemm_fused<1, 1><<<ggrid, 256>>>(N, NCOLS, z, nullptr, scale, shift,
                                     W1b, b1b, h1, nullptr, nullptr, nullptr);

    // ---------------- Layer 2 ----------------
    cudaMemsetAsync(agg,   0, (size_t)N * NCOLS * sizeof(float));
    cudaMemsetAsync(stats, 0, 2 * NCOLS * sizeof(float));
    scatter_kernel<<<scatterBlocks, 256>>>(h1, srcI, dstI, agg, E, NCOLS / 4);
    gemm_fused<0, 0><<<ggrid, 256>>>(N, NCOLS, h1, agg, nullptr, nullptr,
                                     W2a, b2a, z, stats, nullptr, nullptr);
    bn_finalize<<<1, NCOLS>>>(stats, g2, be2, scale, shift, 1.0f / N);
    cudaMemsetAsync(pooled, 0, (size_t)G * NCOLS * sizeof(float));
    gemm_fused<1, 2><<<ggrid, 256>>>(N, NCOLS, z, nullptr, scale, shift,
                                     W2b, b2b, nullptr, nullptr, pooled, batchI);

    // ---------------- Head ----------------
    head_kernel<<<G, NCOLS>>>(pooled, Wl1, bl1, Wl2, bl2, out, OUTC);
}

// round 5
// speedup vs baseline: 1.8523x; 1.8523x over previous
#include <cuda_runtime.h>
#include <cstdint>
#include <cstddef>

// Problem constants (shapes fixed by the dataset)
#define NNODES 50000
#define NEDGES 800000
#define NCOLS  512
#define NGRAPH 64

// ---------------------------------------------------------------------------
// Scratch (device globals; no allocation allowed)
// ---------------------------------------------------------------------------
__device__ float g_agg[(size_t)NNODES * NCOLS];
__device__ float g_z[(size_t)NNODES * NCOLS];
__device__ float g_h1[(size_t)NNODES * NCOLS];
__device__ float g_stats[2 * NCOLS];
__device__ float g_scale[NCOLS];
__device__ float g_shift[NCOLS];
__device__ float g_pooled[(size_t)NGRAPH * NCOLS];
__device__ int   g_src[NEDGES];
__device__ int   g_dst[NEDGES];
__device__ int   g_batch[NNODES];
__device__ int   g_is64;
__device__ float g_Wt1a[(size_t)NCOLS * 128];   // [N=512][K=128]
__device__ float g_Wt1b[(size_t)NCOLS * NCOLS]; // [512][512]
__device__ float g_Wt2a[(size_t)NCOLS * NCOLS];
__device__ float g_Wt2b[(size_t)NCOLS * NCOLS];

// ---------------------------------------------------------------------------
// PTX helpers
// ---------------------------------------------------------------------------
__device__ __forceinline__ uint32_t f2tf32(float f) {
    uint32_t u;
    asm("cvt.rna.tf32.f32 %0, %1;" : "=r"(u) : "f"(f));
    return u;
}
__device__ __forceinline__ void red_add_v4(float* addr, float4 v) {
    asm volatile("red.global.add.v4.f32 [%0], {%1, %2, %3, %4};"
                 :: "l"(addr), "f"(v.x), "f"(v.y), "f"(v.z), "f"(v.w)
                 : "memory");
}
__device__ __forceinline__ void red_add_v2(float* addr, float a, float b) {
    asm volatile("red.global.add.v2.f32 [%0], {%1, %2};"
                 :: "l"(addr), "f"(a), "f"(b) : "memory");
}
__device__ __forceinline__ void mma_m16n8k8(float* c, const uint32_t* a,
                                            uint32_t b0, uint32_t b1) {
    asm volatile("mma.sync.aligned.m16n8k8.row.col.f32.tf32.tf32.f32 "
                 "{%0,%1,%2,%3}, {%4,%5,%6,%7}, {%8,%9}, {%0,%1,%2,%3};"
                 : "+f"(c[0]), "+f"(c[1]), "+f"(c[2]), "+f"(c[3])
                 : "r"(a[0]), "r"(a[1]), "r"(a[2]), "r"(a[3]),
                   "r"(b0), "r"(b1));
}

// ---------------------------------------------------------------------------
// Index dtype detection + canonicalization (int32 vs int64 input)
// ---------------------------------------------------------------------------
__global__ void detect_kernel(const unsigned* __restrict__ ei_words)
{
    unsigned v = ei_words[2 * threadIdx.x + 1];
    unsigned any = __ballot_sync(0xffffffffu, v != 0u);
    __shared__ int s_any;
    if (threadIdx.x == 0) s_any = 0;
    __syncthreads();
    if ((threadIdx.x & 31) == 0 && any) atomicOr(&s_any, 1);
    __syncthreads();
    if (threadIdx.x == 0) g_is64 = (s_any == 0) ? 1 : 0;
}

__global__ void convert_kernel(const void* __restrict__ ei,
                               const void* __restrict__ batch,
                               int E, int N)
{
    int i = blockIdx.x * blockDim.x + threadIdx.x;
    int is64 = g_is64;
    if (i < E) {
        if (is64) {
            g_src[i] = (int)((const long long*)ei)[i];
            g_dst[i] = (int)((const long long*)ei)[E + i];
        } else {
            g_src[i] = ((const int*)ei)[i];
            g_dst[i] = ((const int*)ei)[E + i];
        }
    }
    if (i < N) {
        g_batch[i] = is64 ? (int)((const long long*)batch)[i]
                          : ((const int*)batch)[i];
    }
}

// ---------------------------------------------------------------------------
// Weight transpose: Wt[n][k] = W[k][n].  W is [K][Nw] row-major, Nw = 512.
// ---------------------------------------------------------------------------
__global__ void transpose_kernel(const float* __restrict__ W,
                                 float* __restrict__ Wt, int K, int Nw)
{
    __shared__ float t[32][33];
    int bx = blockIdx.x * 32;   // n block
    int by = blockIdx.y * 32;   // k block
    int x = threadIdx.x, y = threadIdx.y;
    #pragma unroll
    for (int i = 0; i < 32; i += 8)
        t[y + i][x] = W[(size_t)(by + y + i) * Nw + bx + x];
    __syncthreads();
    #pragma unroll
    for (int i = 0; i < 32; i += 8)
        Wt[(size_t)(bx + y + i) * K + by + x] = t[x][y + i];
}

// ---------------------------------------------------------------------------
// Edge scatter: agg[dst] += feat[src].  One warp per edge, red.v4.
// ---------------------------------------------------------------------------
__global__ void scatter_kernel(const float* __restrict__ feat,
                               const int* __restrict__ src,
                               const int* __restrict__ dst,
                               float* __restrict__ agg,
                               int E, int W4)
{
    int warp = (blockIdx.x * blockDim.x + threadIdx.x) >> 5;
    int lane = threadIdx.x & 31;
    if (warp >= E) return;
    int s = src[warp];
    int d = dst[warp];
    const float4* xs = reinterpret_cast<const float4*>(feat) + (size_t)s * W4;
    float*        ad = agg + (size_t)d * (W4 * 4);
    for (int c = lane; c < W4; c += 32) {
        float4 v = xs[c];
        red_add_v4(ad + c * 4, v);
    }
}

// ---------------------------------------------------------------------------
// tf32 mma.sync GEMM: D[128,128] per block = Apre[128,K] @ Bt[col0..][K]^T
//   AM==0 : Apre = A0 + A1
//   AM==1 : Apre = relu(A0 * scale[k] + shift[k])
//   EM==0 : store C = acc            (pre-BN z; layer-a bias is a BN no-op)
//   EM==1 : store C = relu(acc + bias)
//   EM==2 : red-add relu(acc + bias) into pooled[batch[m]]
// 256 threads = 8 warps in a 4x2 grid of 32x64 warp tiles; BK=32.
// SMEM rows padded to 36 floats -> conflict-free frag loads, 16B-aligned v4.
// ---------------------------------------------------------------------------
#define BKP 36

template<int AM, int EM>
__global__ void __launch_bounds__(256, 2)
mma_gemm(const int M, const int K,
         const float* __restrict__ A0, const float* __restrict__ A1,
         const float* __restrict__ scale, const float* __restrict__ shift,
         const float* __restrict__ Bt, const float* __restrict__ bias,
         float* __restrict__ C, float* __restrict__ pooled,
         const int* __restrict__ batch)
{
    __shared__ __align__(16) uint32_t As[128 * BKP];
    __shared__ __align__(16) uint32_t Bs[128 * BKP];

    const int tid  = threadIdx.x;
    const int lane = tid & 31;
    const int warp = tid >> 5;
    const int grp  = lane >> 2;      // 0..7
    const int tig  = lane & 3;       // 0..3
    const int wm   = (warp >> 1) * 32;   // warp m offset (0,32,64,96)
    const int wn   = (warp & 1) * 64;    // warp n offset (0,64)
    const int row0 = blockIdx.x * 128;
    const int col0 = blockIdx.y * 128;

    float acc[2][8][4];
    #pragma unroll
    for (int mt = 0; mt < 2; mt++)
        #pragma unroll
        for (int nt = 0; nt < 8; nt++)
            #pragma unroll
            for (int q = 0; q < 4; q++) acc[mt][nt][q] = 0.f;

    const int slotRow = tid >> 3;        // 0..31 -> x4 = 128 rows
    const int slotC4  = tid & 7;         // 0..7  -> k = c4*4

    for (int k0 = 0; k0 < K; k0 += 32) {
        // ---- load A tile (fused pre-op), tf32-convert into SMEM ----
        #pragma unroll
        for (int r = 0; r < 4; r++) {
            int row = slotRow + r * 32;
            int gr  = row0 + row;
            float4 v = make_float4(0.f, 0.f, 0.f, 0.f);
            if (gr < M) {
                size_t off = (size_t)gr * K + k0 + slotC4 * 4;
                v = *reinterpret_cast<const float4*>(A0 + off);
                if (AM == 0) {
                    float4 w = *reinterpret_cast<const float4*>(A1 + off);
                    v.x += w.x; v.y += w.y; v.z += w.z; v.w += w.w;
                } else {
                    float4 sc = *reinterpret_cast<const float4*>(scale + k0 + slotC4 * 4);
                    float4 sh = *reinterpret_cast<const float4*>(shift + k0 + slotC4 * 4);
                    v.x = fmaxf(fmaf(v.x, sc.x, sh.x), 0.f);
                    v.y = fmaxf(fmaf(v.y, sc.y, sh.y), 0.f);
                    v.z = fmaxf(fmaf(v.z, sc.z, sh.z), 0.f);
                    v.w = fmaxf(fmaf(v.w, sc.w, sh.w), 0.f);
                }
            }
            *reinterpret_cast<uint4*>(&As[row * BKP + slotC4 * 4]) =
                make_uint4(f2tf32(v.x), f2tf32(v.y), f2tf32(v.z), f2tf32(v.w));
        }
        // ---- load B tile ([n][k] K-major global) ----
        #pragma unroll
        for (int r = 0; r < 4; r++) {
            int n = slotRow + r * 32;
            size_t off = (size_t)(col0 + n) * K + k0 + slotC4 * 4;
            float4 v = *reinterpret_cast<const float4*>(Bt + off);
            *reinterpret_cast<uint4*>(&Bs[n * BKP + slotC4 * 4]) =
                make_uint4(f2tf32(v.x), f2tf32(v.y), f2tf32(v.z), f2tf32(v.w));
        }
        __syncthreads();

        #pragma unroll
        for (int ks = 0; ks < 4; ks++) {
            const int kk = ks * 8;
            uint32_t a[2][4];
            #pragma unroll
            for (int mt = 0; mt < 2; mt++) {
                int rbase = (wm + mt * 16 + grp) * BKP + kk;
                a[mt][0] = As[rbase + tig];
                a[mt][1] = As[rbase + 8 * BKP + tig];
                a[mt][2] = As[rbase + tig + 4];
                a[mt][3] = As[rbase + 8 * BKP + tig + 4];
            }
            #pragma unroll
            for (int nt = 0; nt < 8; nt++) {
                int nbase = (wn + nt * 8 + grp) * BKP + kk;
                uint32_t b0 = Bs[nbase + tig];
                uint32_t b1 = Bs[nbase + tig + 4];
                mma_m16n8k8(acc[0][nt], a[0], b0, b1);
                mma_m16n8k8(acc[1][nt], a[1], b0, b1);
            }
        }
        __syncthreads();
    }

    // ---- epilogue ----
    #pragma unroll
    for (int mt = 0; mt < 2; mt++) {
        #pragma unroll
        for (int half = 0; half < 2; half++) {        // c{0,1} then c{2,3}
            int gm = row0 + wm + mt * 16 + grp + half * 8;
            if (gm >= M) continue;
            float* crow;
            if (EM == 2) crow = pooled + (size_t)batch[gm] * NCOLS;
            else         crow = C + (size_t)gm * NCOLS;
            #pragma unroll
            for (int nt = 0; nt < 8; nt++) {
                int col = col0 + wn + nt * 8 + 2 * tig;
                float v0 = acc[mt][nt][2 * half];
                float v1 = acc[mt][nt][2 * half + 1];
                if (EM != 0) {
                    v0 = fmaxf(v0 + __ldg(bias + col),     0.f);
                    v1 = fmaxf(v1 + __ldg(bias + col + 1), 0.f);
                }
                if (EM == 2) {
                    red_add_v2(crow + col, v0, v1);
                } else {
                    *reinterpret_cast<float2*>(crow + col) = make_float2(v0, v1);
                }
            }
        }
    }
}

// ---------------------------------------------------------------------------
// Column stats over z [M, 512]: sum / sumsq per column (L2-resident pass)
// ---------------------------------------------------------------------------
__global__ void colstats_kernel(const float* __restrict__ z, int M,
                                float* __restrict__ stats)
{
    int c = threadIdx.x;                       // 0..255
    int r0 = blockIdx.x * 128;
    int r1 = r0 + 128; if (r1 > M) r1 = M;
    float s0 = 0.f, q0 = 0.f, s1 = 0.f, q1 = 0.f;
    for (int r = r0; r < r1; r++) {
        float a = z[(size_t)r * NCOLS + c];
        float b = z[(size_t)r * NCOLS + c + 256];
        s0 += a; q0 += a * a;
        s1 += b; q1 += b * b;
    }
    atomicAdd(&stats[c],               s0);
    atomicAdd(&stats[c + 256],         s1);
    atomicAdd(&stats[NCOLS + c],       q0);
    atomicAdd(&stats[NCOLS + c + 256], q1);
}

// ---------------------------------------------------------------------------
// BN stats -> fused scale/shift
// ---------------------------------------------------------------------------
__global__ void bn_finalize(const float* __restrict__ stats,
                            const float* __restrict__ gamma,
                            const float* __restrict__ beta,
                            float* __restrict__ scale,
                            float* __restrict__ shift,
                            float invN)
{
    int c = threadIdx.x;
    float mean = stats[c] * invN;
    float var  = stats[NCOLS + c] * invN - mean * mean;
    float s = gamma[c] * rsqrtf(var + 1e-5f);
    scale[c] = s;
    shift[c] = beta[c] - mean * s;
}

// ---------------------------------------------------------------------------
// Head MLP: out = relu(pooled @ Wl1 + bl1) @ Wl2 + bl2   (64 x 10)
// ---------------------------------------------------------------------------
__global__ void head_kernel(const float* __restrict__ pooled,
                            const float* __restrict__ Wl1,
                            const float* __restrict__ bl1,
                            const float* __restrict__ Wl2,
                            const float* __restrict__ bl2,
                            float* __restrict__ out, int OUTC)
{
    __shared__ float sp[NCOLS];
    __shared__ float sh[NCOLS];
    int g = blockIdx.x, t = threadIdx.x;
    sp[t] = pooled[(size_t)g * NCOLS + t];
    __syncthreads();
    float a = bl1[t];
    for (int k = 0; k < NCOLS; k++)
        a = fmaf(sp[k], Wl1[(size_t)k * NCOLS + t], a);
    sh[t] = fmaxf(a, 0.f);
    __syncthreads();
    if (t < 32 * OUTC) {
        int w = t >> 5, l = t & 31;
        float s = 0.f;
        for (int k = l; k < NCOLS; k += 32)
            s = fmaf(sh[k], Wl2[(size_t)k * OUTC + w], s);
        #pragma unroll
        for (int o = 16; o; o >>= 1)
            s += __shfl_down_sync(0xffffffffu, s, o);
        if (l == 0) out[(size_t)g * OUTC + w] = s + bl2[w];
    }
}

// ---------------------------------------------------------------------------
// Launch
// ---------------------------------------------------------------------------
extern "C" void kernel_launch(void* const* d_in, const int* in_sizes, int n_in,
                              void* d_out, int out_size)
{
    const float* x     = (const float*)d_in[0];
    const void*  ei    = d_in[1];
    const void*  batch = d_in[2];
    const float* W1a = (const float*)d_in[3];
    const float* g1  = (const float*)d_in[5];
    const float* be1 = (const float*)d_in[6];
    const float* W1b = (const float*)d_in[7];
    const float* b1b = (const float*)d_in[8];
    const float* W2a = (const float*)d_in[9];
    const float* g2  = (const float*)d_in[11];
    const float* be2 = (const float*)d_in[12];
    const float* W2b = (const float*)d_in[13];
    const float* b2b = (const float*)d_in[14];
    const float* Wl1 = (const float*)d_in[15];
    const float* bl1 = (const float*)d_in[16];
    const float* Wl2 = (const float*)d_in[17];
    const float* bl2 = (const float*)d_in[18];
    float* out = (float*)d_out;

    const int IN   = 128;
    const int N    = in_sizes[0] / IN;        // 50000
    const int E    = in_sizes[1] / 2;         // 800000
    const int OUTC = in_sizes[18];            // 10
    const int G    = out_size / OUTC;         // 64

    float *agg, *z, *h1, *stats, *scale, *shift, *pooled;
    float *Wt1a, *Wt1b, *Wt2a, *Wt2b;
    int *srcI, *dstI, *batchI;
    cudaGetSymbolAddress((void**)&agg,    g_agg);
    cudaGetSymbolAddress((void**)&z,      g_z);
    cudaGetSymbolAddress((void**)&h1,     g_h1);
    cudaGetSymbolAddress((void**)&stats,  g_stats);
    cudaGetSymbolAddress((void**)&scale,  g_scale);
    cudaGetSymbolAddress((void**)&shift,  g_shift);
    cudaGetSymbolAddress((void**)&pooled, g_pooled);
    cudaGetSymbolAddress((void**)&srcI,   g_src);
    cudaGetSymbolAddress((void**)&dstI,   g_dst);
    cudaGetSymbolAddress((void**)&batchI, g_batch);
    cudaGetSymbolAddress((void**)&Wt1a,   g_Wt1a);
    cudaGetSymbolAddress((void**)&Wt1b,   g_Wt1b);
    cudaGetSymbolAddress((void**)&Wt2a,   g_Wt2a);
    cudaGetSymbolAddress((void**)&Wt2b,   g_Wt2b);

    // ---- canonicalize indices; transpose weights to [N][K] K-major ----
    detect_kernel<<<1, 128>>>((const unsigned*)ei);
    convert_kernel<<<(E + 255) / 256, 256>>>(ei, batch, E, N);
    {
        dim3 blk(32, 8);
        transpose_kernel<<<dim3(16, IN / 32),    blk>>>(W1a, Wt1a, IN,    NCOLS);
        transpose_kernel<<<dim3(16, NCOLS / 32), blk>>>(W1b, Wt1b, NCOLS, NCOLS);
        transpose_kernel<<<dim3(16, NCOLS / 32), blk>>>(W2a, Wt2a, NCOLS, NCOLS);
        transpose_kernel<<<dim3(16, NCOLS / 32), blk>>>(W2b, Wt2b, NCOLS, NCOLS);
    }

    const dim3 ggrid((N + 127) / 128, 4);     // 391 x 4
    const int scatterBlocks = (E + 7) / 8;
    const int statBlocks = (N + 127) / 128;

    // ---------------- Layer 1 ----------------
    cudaMemsetAsync(agg,   0, (size_t)N * IN * sizeof(float));
    cudaMemsetAsync(stats, 0, 2 * NCOLS * sizeof(float));
    scatter_kernel<<<scatterBlocks, 256>>>(x, srcI, dstI, agg, E, IN / 4);
    mma_gemm<0, 0><<<ggrid, 256>>>(N, IN, x, agg, nullptr, nullptr,
                                   Wt1a, nullptr, z, nullptr, nullptr);
    colstats_kernel<<<statBlocks, 256>>>(z, N, stats);
    bn_finalize<<<1, NCOLS>>>(stats, g1, be1, scale, shift, 1.0f / N);
    mma_gemm<1, 1><<<ggrid, 256>>>(N, NCOLS, z, nullptr, scale, shift,
                                   Wt1b, b1b, h1, nullptr, nullptr);

    // ---------------- Layer 2 ----------------
    cudaMemsetAsync(agg,   0, (size_t)N * NCOLS * sizeof(float));
    cudaMemsetAsync(stats, 0, 2 * NCOLS * sizeof(float));
    scatter_kernel<<<scatterBlocks, 256>>>(h1, srcI, dstI, agg, E, NCOLS / 4);
    mma_gemm<0, 0><<<ggrid, 256>>>(N, NCOLS, h1, agg, nullptr, nullptr,
                                   Wt2a, nullptr, z, nullptr, nullptr);
    colstats_kernel<<<statBlocks, 256>>>(z, N, stats);
    bn_finalize<<<1, NCOLS>>>(stats, g2, be2, scale, shift, 1.0f / N);
    cudaMemsetAsync(pooled, 0, (size_t)G * NCOLS * sizeof(float));
    mma_gemm<1, 2><<<ggrid, 256>>>(N, NCOLS, z, nullptr, scale, shift,
                                   Wt2b, b2b, nullptr, pooled, batchI);

    // ---------------- Head ----------------
    head_kernel<<<G, NCOLS>>>(pooled, Wl1, bl1, Wl2, bl2, out, OUTC);
}

// round 6
// speedup vs baseline: 2.8484x; 1.5377x over previous
#include <cuda_runtime.h>
#include <cstdint>
#include <cstddef>

// Problem constants (shapes fixed by the dataset)
#define NNODES 50000
#define NEDGES 800000
#define NCOLS  512
#define NGRAPH 64

// ---------------------------------------------------------------------------
// Scratch (device globals; no allocation allowed)
// ---------------------------------------------------------------------------
__device__ float g_agg[(size_t)NNODES * NCOLS];     // combined (self+agg)
__device__ float g_z[(size_t)NNODES * NCOLS];
__device__ float g_h1[(size_t)NNODES * NCOLS];
__device__ float g_stats[2 * NCOLS];
__device__ float g_scale[NCOLS];
__device__ float g_shift[NCOLS];
__device__ float g_pooled[(size_t)NGRAPH * NCOLS];
__device__ int   g_src[NEDGES];
__device__ int   g_dst[NEDGES];
__device__ int   g_batch[NNODES];
__device__ int   g_is64;
__device__ int   g_off[NNODES + 1];                 // CSR offsets (by dst)
__device__ int   g_cur[NNODES];                     // deg / cursor
__device__ int   g_ssrc[NEDGES];                    // src sorted by dst
__device__ float g_Wt1a[(size_t)NCOLS * 128];       // [N=512][K] tf32 bits
__device__ float g_Wt1b[(size_t)NCOLS * NCOLS];
__device__ float g_Wt2a[(size_t)NCOLS * NCOLS];
__device__ float g_Wt2b[(size_t)NCOLS * NCOLS];

// ---------------------------------------------------------------------------
// PTX helpers
// ---------------------------------------------------------------------------
__device__ __forceinline__ uint32_t smem_u32(const void* p) {
    uint32_t a;
    asm("{ .reg .u64 t; cvta.to.shared.u64 t, %1; cvt.u32.u64 %0, t; }"
        : "=r"(a) : "l"(p));
    return a;
}
__device__ __forceinline__ uint32_t f2tf32(float f) {
    uint32_t u;
    asm("cvt.rna.tf32.f32 %0, %1;" : "=r"(u) : "f"(f));
    return u;
}
__device__ __forceinline__ void cp16(uint32_t s, const void* g) {
    asm volatile("cp.async.cg.shared.global [%0], [%1], 16;"
                 :: "r"(s), "l"(g) : "memory");
}
__device__ __forceinline__ void red_add_v2(float* addr, float a, float b) {
    asm volatile("red.global.add.v2.f32 [%0], {%1, %2};"
                 :: "l"(addr), "f"(a), "f"(b) : "memory");
}
__device__ __forceinline__ void mma_m16n8k8(float* c, const uint32_t* a,
                                            uint32_t b0, uint32_t b1) {
    asm volatile("mma.sync.aligned.m16n8k8.row.col.f32.tf32.tf32.f32 "
                 "{%0,%1,%2,%3}, {%4,%5,%6,%7}, {%8,%9}, {%0,%1,%2,%3};"
                 : "+f"(c[0]), "+f"(c[1]), "+f"(c[2]), "+f"(c[3])
                 : "r"(a[0]), "r"(a[1]), "r"(a[2]), "r"(a[3]),
                   "r"(b0), "r"(b1));
}

// ---------------------------------------------------------------------------
// Index dtype detection + canonicalization (int32 vs int64 input)
// ---------------------------------------------------------------------------
__global__ void detect_kernel(const unsigned* __restrict__ ei_words)
{
    unsigned v = ei_words[2 * threadIdx.x + 1];
    unsigned any = __ballot_sync(0xffffffffu, v != 0u);
    __shared__ int s_any;
    if (threadIdx.x == 0) s_any = 0;
    __syncthreads();
    if ((threadIdx.x & 31) == 0 && any) atomicOr(&s_any, 1);
    __syncthreads();
    if (threadIdx.x == 0) g_is64 = (s_any == 0) ? 1 : 0;
}

__global__ void convert_kernel(const void* __restrict__ ei,
                               const void* __restrict__ batch,
                               int E, int N)
{
    int i = blockIdx.x * blockDim.x + threadIdx.x;
    int is64 = g_is64;
    if (i < E) {
        if (is64) {
            g_src[i] = (int)((const long long*)ei)[i];
            g_dst[i] = (int)((const long long*)ei)[E + i];
        } else {
            g_src[i] = ((const int*)ei)[i];
            g_dst[i] = ((const int*)ei)[E + i];
        }
    }
    if (i < N) {
        g_batch[i] = is64 ? (int)((const long long*)batch)[i]
                          : ((const int*)batch)[i];
    }
}

// ---------------------------------------------------------------------------
// CSR build: histogram by dst, exclusive scan, reorder src by dst
// ---------------------------------------------------------------------------
__global__ void hist_kernel(int E)
{
    int i = blockIdx.x * blockDim.x + threadIdx.x;
    if (i < E) atomicAdd(&g_cur[g_dst[i]], 1);
}

__global__ void scan_kernel(const int* __restrict__ deg,
                            int* __restrict__ off, int n)
{
    __shared__ int wsum[32];
    __shared__ int carry;
    __shared__ int tileTotal;
    int tid = threadIdx.x;
    if (tid == 0) carry = 0;
    __syncthreads();
    for (int base = 0; base < n; base += 1024) {
        int i = base + tid;
        int v = (i < n) ? deg[i] : 0;
        int x = v;
        #pragma unroll
        for (int o = 1; o < 32; o <<= 1) {
            int y = __shfl_up_sync(0xffffffffu, x, o);
            if ((tid & 31) >= o) x += y;
        }
        if ((tid & 31) == 31) wsum[tid >> 5] = x;
        __syncthreads();
        if (tid < 32) {
            int w = wsum[tid];
            int s = w;
            #pragma unroll
            for (int o = 1; o < 32; o <<= 1) {
                int y = __shfl_up_sync(0xffffffffu, s, o);
                if (tid >= o) s += y;
            }
            wsum[tid] = s - w;              // exclusive warp offsets
            if (tid == 31) tileTotal = s;   // tile total
        }
        __syncthreads();
        int incl = x + wsum[tid >> 5];
        if (i < n) off[i] = carry + incl - v;
        __syncthreads();
        if (tid == 0) carry += tileTotal;
        __syncthreads();
    }
    if (tid == 0) off[n] = carry;
}

__global__ void copy_kernel(const int* __restrict__ a, int* __restrict__ b, int n)
{
    int i = blockIdx.x * blockDim.x + threadIdx.x;
    if (i < n) b[i] = a[i];
}

__global__ void reorder_kernel(int E)
{
    int i = blockIdx.x * blockDim.x + threadIdx.x;
    if (i < E) {
        int d = g_dst[i];
        int p = atomicAdd(&g_cur[d], 1);
        g_ssrc[p] = g_src[i];
    }
}

// ---------------------------------------------------------------------------
// CSR gather: out[v] = feat[v] + sum_{(u,v)} feat[u].  One warp per node.
// R = float4s per lane (1 -> 128 cols, 4 -> 512 cols).
// ---------------------------------------------------------------------------
template<int R>
__global__ void gather_csr(const float* __restrict__ feat,
                           float* __restrict__ out, int Nn)
{
    int v = (blockIdx.x * blockDim.x + threadIdx.x) >> 5;
    int lane = threadIdx.x & 31;
    if (v >= Nn) return;
    int e0 = g_off[v], e1 = g_off[v + 1];
    const float4* fp = reinterpret_cast<const float4*>(feat);
    size_t selfb = (size_t)v * (R * 32);
    float4 acc[R];
    #pragma unroll
    for (int r = 0; r < R; r++) acc[r] = fp[selfb + lane + 32 * r];
    int e = e0;
    for (; e + 1 < e1; e += 2) {
        int sA = g_ssrc[e], sB = g_ssrc[e + 1];
        size_t bA = (size_t)sA * (R * 32), bB = (size_t)sB * (R * 32);
        #pragma unroll
        for (int r = 0; r < R; r++) {
            float4 a = fp[bA + lane + 32 * r];
            float4 b = fp[bB + lane + 32 * r];
            acc[r].x += a.x + b.x; acc[r].y += a.y + b.y;
            acc[r].z += a.z + b.z; acc[r].w += a.w + b.w;
        }
    }
    if (e < e1) {
        size_t bA = (size_t)g_ssrc[e] * (R * 32);
        #pragma unroll
        for (int r = 0; r < R; r++) {
            float4 a = fp[bA + lane + 32 * r];
            acc[r].x += a.x; acc[r].y += a.y; acc[r].z += a.z; acc[r].w += a.w;
        }
    }
    float4* op = reinterpret_cast<float4*>(out);
    #pragma unroll
    for (int r = 0; r < R; r++) op[selfb + lane + 32 * r] = acc[r];
}

// ---------------------------------------------------------------------------
// Weight transpose + tf32 pre-round: Wt[n][k] = tf32(W[k][n])
// ---------------------------------------------------------------------------
__global__ void transpose_kernel(const float* __restrict__ W,
                                 float* __restrict__ Wt, int K, int Nw)
{
    __shared__ float t[32][33];
    int bx = blockIdx.x * 32;   // n block
    int by = blockIdx.y * 32;   // k block
    int x = threadIdx.x, y = threadIdx.y;
    #pragma unroll
    for (int i = 0; i < 32; i += 8)
        t[y + i][x] = W[(size_t)(by + y + i) * Nw + bx + x];
    __syncthreads();
    #pragma unroll
    for (int i = 0; i < 32; i += 8)
        Wt[(size_t)(bx + y + i) * K + by + x] =
            __uint_as_float(f2tf32(t[x][y + i]));
}

// ---------------------------------------------------------------------------
// tf32 mma.sync GEMM with cp.async double buffering.
//   D[128,128] per block = Apre[128,K] @ Bt[col0..][K]^T
//   AM==0 : Apre = A0 (combined already)        AM==1 : relu(A0*scale+shift)
//   EM==0 : store acc    EM==1 : store relu(acc+bias)
//   EM==2 : red-add relu(acc+bias) into pooled[batch[m]]
// 256 threads = 8 warps (4x2 of 32x64 warp tiles); BK=32, 2-stage pipeline.
// Dynamic SMEM: As[2] + Bs[2], each 128 x BKP u32.
// ---------------------------------------------------------------------------
#define BKP 36
#define CH_U32 (128 * BKP)
#define GEMM_SMEM (4 * CH_U32 * 4)      // 73728 B

template<int AM, int EM>
__global__ void __launch_bounds__(256, 2)
mma_gemm(const int M, const int K,
         const float* __restrict__ A0,
         const float* __restrict__ scale, const float* __restrict__ shift,
         const float* __restrict__ Bt, const float* __restrict__ bias,
         float* __restrict__ C, float* __restrict__ pooled,
         const int* __restrict__ batch)
{
    extern __shared__ uint32_t dyn[];
    const uint32_t sbase = smem_u32(dyn);

    const int tid  = threadIdx.x;
    const int lane = tid & 31;
    const int warp = tid >> 5;
    const int grp  = lane >> 2;
    const int tig  = lane & 3;
    const int wm   = (warp >> 1) * 32;
    const int wn   = (warp & 1) * 64;
    const int row0 = blockIdx.x * 128;
    const int col0 = blockIdx.y * 128;

    const int slotRow = tid >> 3;        // 0..31
    const int slotC4  = tid & 7;         // 0..7

    float acc[2][8][4];
    #pragma unroll
    for (int mt = 0; mt < 2; mt++)
        #pragma unroll
        for (int nt = 0; nt < 8; nt++)
            #pragma unroll
            for (int q = 0; q < 4; q++) acc[mt][nt][q] = 0.f;

    const int NC = K >> 5;

    auto cpAB = [&](int ci, int buf) {
        const int k0 = ci << 5;
        #pragma unroll
        for (int r = 0; r < 4; r++) {
            int row = slotRow + r * 32;
            uint32_t so = (uint32_t)(row * BKP + slotC4 * 4) * 4;
            int gr = row0 + row;
            if (gr < M) {
                cp16(sbase + buf * (CH_U32 * 4) + so,
                     A0 + (size_t)gr * K + k0 + slotC4 * 4);
            } else {
                *reinterpret_cast<uint4*>(&dyn[buf * CH_U32 + row * BKP + slotC4 * 4]) =
                    make_uint4(0u, 0u, 0u, 0u);
            }
            cp16(sbase + (2 + buf) * (CH_U32 * 4) + so,
                 Bt + (size_t)(col0 + row) * K + k0 + slotC4 * 4);
        }
        asm volatile("cp.async.commit_group;" ::: "memory");
    };

    auto convertA = [&](int ci, int buf) {
        const int k0 = ci << 5;
        #pragma unroll
        for (int r = 0; r < 4; r++) {
            int row = slotRow + r * 32;
            uint32_t* p = &dyn[buf * CH_U32 + row * BKP + slotC4 * 4];
            float4 v = *reinterpret_cast<float4*>(p);
            if (AM == 1) {
                float4 sc = *reinterpret_cast<const float4*>(scale + k0 + slotC4 * 4);
                float4 sh = *reinterpret_cast<const float4*>(shift + k0 + slotC4 * 4);
                v.x = fmaxf(fmaf(v.x, sc.x, sh.x), 0.f);
                v.y = fmaxf(fmaf(v.y, sc.y, sh.y), 0.f);
                v.z = fmaxf(fmaf(v.z, sc.z, sh.z), 0.f);
                v.w = fmaxf(fmaf(v.w, sc.w, sh.w), 0.f);
            }
            *reinterpret_cast<uint4*>(p) =
                make_uint4(f2tf32(v.x), f2tf32(v.y), f2tf32(v.z), f2tf32(v.w));
        }
    };

    cpAB(0, 0);

    for (int i = 0; i < NC; i++) {
        const int buf = i & 1;
        asm volatile("cp.async.wait_group 0;" ::: "memory");
        __syncthreads();
        convertA(i, buf);
        __syncthreads();
        if (i + 1 < NC) cpAB(i + 1, buf ^ 1);

        const uint32_t* As = &dyn[buf * CH_U32];
        const uint32_t* Bs = &dyn[(2 + buf) * CH_U32];
        #pragma unroll
        for (int ks = 0; ks < 4; ks++) {
            const int kk = ks * 8;
            uint32_t a[2][4];
            #pragma unroll
            for (int mt = 0; mt < 2; mt++) {
                int rbase = (wm + mt * 16 + grp) * BKP + kk;
                a[mt][0] = As[rbase + tig];
                a[mt][1] = As[rbase + 8 * BKP + tig];
                a[mt][2] = As[rbase + tig + 4];
                a[mt][3] = As[rbase + 8 * BKP + tig + 4];
            }
            #pragma unroll
            for (int nt = 0; nt < 8; nt++) {
                int nbase = (wn + nt * 8 + grp) * BKP + kk;
                uint32_t b0 = Bs[nbase + tig];
                uint32_t b1 = Bs[nbase + tig + 4];
                mma_m16n8k8(acc[0][nt], a[0], b0, b1);
                mma_m16n8k8(acc[1][nt], a[1], b0, b1);
            }
        }
        __syncthreads();
    }

    // ---- epilogue ----
    #pragma unroll
    for (int mt = 0; mt < 2; mt++) {
        #pragma unroll
        for (int half = 0; half < 2; half++) {
            int gm = row0 + wm + mt * 16 + grp + half * 8;
            if (gm >= M) continue;
            float* crow;
            if (EM == 2) crow = pooled + (size_t)batch[gm] * NCOLS;
            else         crow = C + (size_t)gm * NCOLS;
            #pragma unroll
            for (int nt = 0; nt < 8; nt++) {
                int col = col0 + wn + nt * 8 + 2 * tig;
                float v0 = acc[mt][nt][2 * half];
                float v1 = acc[mt][nt][2 * half + 1];
                if (EM != 0) {
                    v0 = fmaxf(v0 + __ldg(bias + col),     0.f);
                    v1 = fmaxf(v1 + __ldg(bias + col + 1), 0.f);
                }
                if (EM == 2) {
                    red_add_v2(crow + col, v0, v1);
                } else {
                    *reinterpret_cast<float2*>(crow + col) = make_float2(v0, v1);
                }
            }
        }
    }
}

// ---------------------------------------------------------------------------
// Column stats over z [M, 512]: sum / sumsq per column
// ---------------------------------------------------------------------------
__global__ void colstats_kernel(const float* __restrict__ z, int M,
                                float* __restrict__ stats)
{
    int c = threadIdx.x;
    int r0 = blockIdx.x * 128;
    int r1 = r0 + 128; if (r1 > M) r1 = M;
    float s0 = 0.f, q0 = 0.f, s1 = 0.f, q1 = 0.f;
    for (int r = r0; r < r1; r++) {
        float a = z[(size_t)r * NCOLS + c];
        float b = z[(size_t)r * NCOLS + c + 256];
        s0 += a; q0 += a * a;
        s1 += b; q1 += b * b;
    }
    atomicAdd(&stats[c],               s0);
    atomicAdd(&stats[c + 256],         s1);
    atomicAdd(&stats[NCOLS + c],       q0);
    atomicAdd(&stats[NCOLS + c + 256], q1);
}

// ---------------------------------------------------------------------------
// BN stats -> fused scale/shift
// ---------------------------------------------------------------------------
__global__ void bn_finalize(const float* __restrict__ stats,
                            const float* __restrict__ gamma,
                            const float* __restrict__ beta,
                            float* __restrict__ scale,
                            float* __restrict__ shift,
                            float invN)
{
    int c = threadIdx.x;
    float mean = stats[c] * invN;
    float var  = stats[NCOLS + c] * invN - mean * mean;
    float s = gamma[c] * rsqrtf(var + 1e-5f);
    scale[c] = s;
    shift[c] = beta[c] - mean * s;
}

// ---------------------------------------------------------------------------
// Head MLP: out = relu(pooled @ Wl1 + bl1) @ Wl2 + bl2   (64 x 10)
// ---------------------------------------------------------------------------
__global__ void head_kernel(const float* __restrict__ pooled,
                            const float* __restrict__ Wl1,
                            const float* __restrict__ bl1,
                            const float* __restrict__ Wl2,
                            const float* __restrict__ bl2,
                            float* __restrict__ out, int OUTC)
{
    __shared__ float sp[NCOLS];
    __shared__ float sh[NCOLS];
    int g = blockIdx.x, t = threadIdx.x;
    sp[t] = pooled[(size_t)g * NCOLS + t];
    __syncthreads();
    float a = bl1[t];
    for (int k = 0; k < NCOLS; k++)
        a = fmaf(sp[k], Wl1[(size_t)k * NCOLS + t], a);
    sh[t] = fmaxf(a, 0.f);
    __syncthreads();
    if (t < 32 * OUTC) {
        int w = t >> 5, l = t & 31;
        float s = 0.f;
        for (int k = l; k < NCOLS; k += 32)
            s = fmaf(sh[k], Wl2[(size_t)k * OUTC + w], s);
        #pragma unroll
        for (int o = 16; o; o >>= 1)
            s += __shfl_down_sync(0xffffffffu, s, o);
        if (l == 0) out[(size_t)g * OUTC + w] = s + bl2[w];
    }
}

// ---------------------------------------------------------------------------
// Launch
// ---------------------------------------------------------------------------
extern "C" void kernel_launch(void* const* d_in, const int* in_sizes, int n_in,
                              void* d_out, int out_size)
{
    const float* x     = (const float*)d_in[0];
    const void*  ei    = d_in[1];
    const void*  batch = d_in[2];
    const float* W1a = (const float*)d_in[3];
    const float* g1  = (const float*)d_in[5];
    const float* be1 = (const float*)d_in[6];
    const float* W1b = (const float*)d_in[7];
    const float* b1b = (const float*)d_in[8];
    const float* W2a = (const float*)d_in[9];
    const float* g2  = (const float*)d_in[11];
    const float* be2 = (const float*)d_in[12];
    const float* W2b = (const float*)d_in[13];
    const float* b2b = (const float*)d_in[14];
    const float* Wl1 = (const float*)d_in[15];
    const float* bl1 = (const float*)d_in[16];
    const float* Wl2 = (const float*)d_in[17];
    const float* bl2 = (const float*)d_in[18];
    float* out = (float*)d_out;

    const int IN   = 128;
    const int N    = in_sizes[0] / IN;        // 50000
    const int E    = in_sizes[1] / 2;         // 800000
    const int OUTC = in_sizes[18];            // 10
    const int G    = out_size / OUTC;         // 64

    float *comb, *z, *h1, *stats, *scale, *shift, *pooled;
    float *Wt1a, *Wt1b, *Wt2a, *Wt2b;
    int *batchI, *offI, *curI;
    cudaGetSymbolAddress((void**)&comb,   g_agg);
    cudaGetSymbolAddress((void**)&z,      g_z);
    cudaGetSymbolAddress((void**)&h1,     g_h1);
    cudaGetSymbolAddress((void**)&stats,  g_stats);
    cudaGetSymbolAddress((void**)&scale,  g_scale);
    cudaGetSymbolAddress((void**)&shift,  g_shift);
    cudaGetSymbolAddress((void**)&pooled, g_pooled);
    cudaGetSymbolAddress((void**)&batchI, g_batch);
    cudaGetSymbolAddress((void**)&offI,   g_off);
    cudaGetSymbolAddress((void**)&curI,   g_cur);
    cudaGetSymbolAddress((void**)&Wt1a,   g_Wt1a);
    cudaGetSymbolAddress((void**)&Wt1b,   g_Wt1b);
    cudaGetSymbolAddress((void**)&Wt2a,   g_Wt2a);
    cudaGetSymbolAddress((void**)&Wt2b,   g_Wt2b);

    cudaFuncSetAttribute(mma_gemm<0, 0>, cudaFuncAttributeMaxDynamicSharedMemorySize, GEMM_SMEM);
    cudaFuncSetAttribute(mma_gemm<1, 1>, cudaFuncAttributeMaxDynamicSharedMemorySize, GEMM_SMEM);
    cudaFuncSetAttribute(mma_gemm<1, 2>, cudaFuncAttributeMaxDynamicSharedMemorySize, GEMM_SMEM);

    // ---- canonicalize indices; build CSR; transpose weights (tf32) ----
    detect_kernel<<<1, 128>>>((const unsigned*)ei);
    convert_kernel<<<(E + 255) / 256, 256>>>(ei, batch, E, N);
    cudaMemsetAsync(curI, 0, (size_t)N * sizeof(int));
    hist_kernel<<<(E + 255) / 256, 256>>>(E);
    scan_kernel<<<1, 1024>>>(curI, offI, N);
    copy_kernel<<<(N + 255) / 256, 256>>>(offI, curI, N);
    reorder_kernel<<<(E + 255) / 256, 256>>>(E);
    {
        dim3 blk(32, 8);
        transpose_kernel<<<dim3(16, IN / 32),    blk>>>(W1a, Wt1a, IN,    NCOLS);
        transpose_kernel<<<dim3(16, NCOLS / 32), blk>>>(W1b, Wt1b, NCOLS, NCOLS);
        transpose_kernel<<<dim3(16, NCOLS / 32), blk>>>(W2a, Wt2a, NCOLS, NCOLS);
        transpose_kernel<<<dim3(16, NCOLS / 32), blk>>>(W2b, Wt2b, NCOLS, NCOLS);
    }

    const dim3 ggrid((N + 127) / 128, 4);
    const int gatherBlocks = (N * 32 + 255) / 256;
    const int statBlocks = (N + 127) / 128;

    // ---------------- Layer 1 ----------------
    cudaMemsetAsync(stats, 0, 2 * NCOLS * sizeof(float));
    gather_csr<1><<<gatherBlocks, 256>>>(x, comb, N);
    mma_gemm<0, 0><<<ggrid, 256, GEMM_SMEM>>>(N, IN, comb, nullptr, nullptr,
                                              Wt1a, nullptr, z, nullptr, nullptr);
    colstats_kernel<<<statBlocks, 256>>>(z, N, stats);
    bn_finalize<<<1, NCOLS>>>(stats, g1, be1, scale, shift, 1.0f / N);
    mma_gemm<1, 1><<<ggrid, 256, GEMM_SMEM>>>(N, NCOLS, z, scale, shift,
                                              Wt1b, b1b, h1, nullptr, nullptr);

    // ---------------- Layer 2 ----------------
    cudaMemsetAsync(stats, 0, 2 * NCOLS * sizeof(float));
    gather_csr<4><<<gatherBlocks, 256>>>(h1, comb, N);
    mma_gemm<0, 0><<<ggrid, 256, GEMM_SMEM>>>(N, NCOLS, comb, nullptr, nullptr,
                                              Wt2a, nullptr, z, nullptr, nullptr);
    colstats_kernel<<<statBlocks, 256>>>(z, N, stats);
    bn_finalize<<<1, NCOLS>>>(stats, g2, be2, scale, shift, 1.0f / N);
    cudaMemsetAsync(pooled, 0, (size_t)G * NCOLS * sizeof(float));
    mma_gemm<1, 2><<<ggrid, 256, GEMM_SMEM>>>(N, NCOLS, z, scale, shift,
                                              Wt2b, b2b, nullptr, pooled, batchI);

    // ---------------- Head ----------------
    head_kernel<<<G, NCOLS>>>(pooled, Wl1, bl1, Wl2, bl2, out, OUTC);
}

// round 7
// speedup vs baseline: 3.2265x; 1.1328x over previous
#include <cuda_runtime.h>
#include <cstdint>
#include <cstddef>

// Problem constants (shapes fixed by the dataset)
#define NNODES 50000
#define NEDGES 800000
#define NCOLS  512
#define NGRAPH 64

// ---------------------------------------------------------------------------
// Scratch (device globals; no allocation allowed)
// ---------------------------------------------------------------------------
__device__ float g_agg[(size_t)NNODES * NCOLS];     // combined (self+agg), tf32-rounded
__device__ float g_z[(size_t)NNODES * NCOLS];
__device__ float g_h1[(size_t)NNODES * NCOLS];
__device__ float g_stats[2 * NCOLS];
__device__ float g_scale[NCOLS];
__device__ float g_shift[NCOLS];
__device__ float g_pooled[(size_t)NGRAPH * NCOLS];
__device__ int   g_src[NEDGES];
__device__ int   g_dst[NEDGES];
__device__ int   g_batch[NNODES];
__device__ int   g_is64;
__device__ int   g_off[NNODES + 1];                 // CSR offsets (by dst)
__device__ int   g_cur[NNODES];                     // deg / cursor
__device__ int   g_bsum[64];                        // scan block sums
__device__ int   g_ssrc[NEDGES];                    // src sorted by dst
__device__ float g_Wt1a[(size_t)NCOLS * 128];       // [N=512][K] tf32 bits
__device__ float g_Wt1b[(size_t)NCOLS * NCOLS];
__device__ float g_Wt2a[(size_t)NCOLS * NCOLS];
__device__ float g_Wt2b[(size_t)NCOLS * NCOLS];

// ---------------------------------------------------------------------------
// PTX helpers
// ---------------------------------------------------------------------------
__device__ __forceinline__ uint32_t smem_u32(const void* p) {
    uint32_t a;
    asm("{ .reg .u64 t; cvta.to.shared.u64 t, %1; cvt.u32.u64 %0, t; }"
        : "=r"(a) : "l"(p));
    return a;
}
__device__ __forceinline__ uint32_t f2tf32(float f) {
    uint32_t u;
    asm("cvt.rna.tf32.f32 %0, %1;" : "=r"(u) : "f"(f));
    return u;
}
__device__ __forceinline__ float4 round_tf32x4(float4 v) {
    return make_float4(__uint_as_float(f2tf32(v.x)), __uint_as_float(f2tf32(v.y)),
                       __uint_as_float(f2tf32(v.z)), __uint_as_float(f2tf32(v.w)));
}
__device__ __forceinline__ void cp16(uint32_t s, const void* g) {
    asm volatile("cp.async.cg.shared.global [%0], [%1], 16;"
                 :: "r"(s), "l"(g) : "memory");
}
__device__ __forceinline__ void red_add_v2(float* addr, float a, float b) {
    asm volatile("red.global.add.v2.f32 [%0], {%1, %2};"
                 :: "l"(addr), "f"(a), "f"(b) : "memory");
}
__device__ __forceinline__ void mma_m16n8k8(float* c, const uint32_t* a,
                                            uint32_t b0, uint32_t b1) {
    asm volatile("mma.sync.aligned.m16n8k8.row.col.f32.tf32.tf32.f32 "
                 "{%0,%1,%2,%3}, {%4,%5,%6,%7}, {%8,%9}, {%0,%1,%2,%3};"
                 : "+f"(c[0]), "+f"(c[1]), "+f"(c[2]), "+f"(c[3])
                 : "r"(a[0]), "r"(a[1]), "r"(a[2]), "r"(a[3]),
                   "r"(b0), "r"(b1));
}

// ---------------------------------------------------------------------------
// Index dtype detection + canonicalization (int32 vs int64 input)
// ---------------------------------------------------------------------------
__global__ void detect_kernel(const unsigned* __restrict__ ei_words)
{
    unsigned v = ei_words[2 * threadIdx.x + 1];
    unsigned any = __ballot_sync(0xffffffffu, v != 0u);
    __shared__ int s_any;
    if (threadIdx.x == 0) s_any = 0;
    __syncthreads();
    if ((threadIdx.x & 31) == 0 && any) atomicOr(&s_any, 1);
    __syncthreads();
    if (threadIdx.x == 0) g_is64 = (s_any == 0) ? 1 : 0;
}

__global__ void convert_kernel(const void* __restrict__ ei,
                               const void* __restrict__ batch,
                               int E, int N)
{
    int i = blockIdx.x * blockDim.x + threadIdx.x;
    int is64 = g_is64;
    if (i < E) {
        if (is64) {
            g_src[i] = (int)((const long long*)ei)[i];
            g_dst[i] = (int)((const long long*)ei)[E + i];
        } else {
            g_src[i] = ((const int*)ei)[i];
            g_dst[i] = ((const int*)ei)[E + i];
        }
    }
    if (i < N) {
        g_batch[i] = is64 ? (int)((const long long*)batch)[i]
                          : ((const int*)batch)[i];
    }
}

// ---------------------------------------------------------------------------
// CSR build: histogram by dst, 3-phase parallel exclusive scan, reorder
// ---------------------------------------------------------------------------
__global__ void hist_kernel(int E)
{
    int i = blockIdx.x * blockDim.x + threadIdx.x;
    if (i < E) atomicAdd(&g_cur[g_dst[i]], 1);
}

__global__ void scan_block(const int* __restrict__ deg, int* __restrict__ off,
                           int* __restrict__ bsum, int n)
{
    __shared__ int wsum[32];
    __shared__ int woff[32];
    __shared__ int total;
    int tid = threadIdx.x, lane = tid & 31, wid = tid >> 5;
    int i = blockIdx.x * 1024 + tid;
    int v = (i < n) ? deg[i] : 0;
    int x = v;
    #pragma unroll
    for (int o = 1; o < 32; o <<= 1) {
        int y = __shfl_up_sync(0xffffffffu, x, o);
        if (lane >= o) x += y;
    }
    if (lane == 31) wsum[wid] = x;
    __syncthreads();
    if (tid < 32) {
        int w = wsum[tid];
        int s = w;
        #pragma unroll
        for (int o = 1; o < 32; o <<= 1) {
            int y = __shfl_up_sync(0xffffffffu, s, o);
            if (tid >= o) s += y;
        }
        woff[tid] = s - w;
        if (tid == 31) total = s;
    }
    __syncthreads();
    if (i < n) off[i] = x + woff[wid] - v;     // block-local exclusive
    if (tid == 0) bsum[blockIdx.x] = total;
}

__global__ void scan_tops(int* __restrict__ bsum, int nb)
{
    __shared__ int sh[64];
    int tid = threadIdx.x;
    int v = (tid < nb) ? bsum[tid] : 0;
    sh[tid] = v;
    __syncthreads();
    #pragma unroll
    for (int o = 1; o < 64; o <<= 1) {
        int t = (tid >= o) ? sh[tid - o] : 0;
        __syncthreads();
        sh[tid] += t;
        __syncthreads();
    }
    if (tid < nb) bsum[tid] = sh[tid] - v;     // exclusive
}

__global__ void scan_add(int* __restrict__ off, const int* __restrict__ bsum,
                         int n, int E)
{
    int i = blockIdx.x * 1024 + threadIdx.x;
    if (i < n) off[i] += bsum[blockIdx.x];
    if (i == 0) off[n] = E;
}

__global__ void copy_kernel(const int* __restrict__ a, int* __restrict__ b, int n)
{
    int i = blockIdx.x * blockDim.x + threadIdx.x;
    if (i < n) b[i] = a[i];
}

__global__ void reorder_kernel(int E)
{
    int i = blockIdx.x * blockDim.x + threadIdx.x;
    if (i < E) {
        int d = g_dst[i];
        int p = atomicAdd(&g_cur[d], 1);
        g_ssrc[p] = g_src[i];
    }
}

// ---------------------------------------------------------------------------
// CSR gather: out[v] = tf32(feat[v] + sum_{(u,v)} feat[u]).  One warp per node.
// ---------------------------------------------------------------------------
template<int R>
__global__ void gather_csr(const float* __restrict__ feat,
                           float* __restrict__ out, int Nn)
{
    int v = (blockIdx.x * blockDim.x + threadIdx.x) >> 5;
    int lane = threadIdx.x & 31;
    if (v >= Nn) return;
    int e0 = g_off[v], e1 = g_off[v + 1];
    const float4* fp = reinterpret_cast<const float4*>(feat);
    size_t selfb = (size_t)v * (R * 32);
    float4 acc[R];
    #pragma unroll
    for (int r = 0; r < R; r++) acc[r] = fp[selfb + lane + 32 * r];
    int e = e0;
    for (; e + 1 < e1; e += 2) {
        int sA = g_ssrc[e], sB = g_ssrc[e + 1];
        size_t bA = (size_t)sA * (R * 32), bB = (size_t)sB * (R * 32);
        #pragma unroll
        for (int r = 0; r < R; r++) {
            float4 a = fp[bA + lane + 32 * r];
            float4 b = fp[bB + lane + 32 * r];
            acc[r].x += a.x + b.x; acc[r].y += a.y + b.y;
            acc[r].z += a.z + b.z; acc[r].w += a.w + b.w;
        }
    }
    if (e < e1) {
        size_t bA = (size_t)g_ssrc[e] * (R * 32);
        #pragma unroll
        for (int r = 0; r < R; r++) {
            float4 a = fp[bA + lane + 32 * r];
            acc[r].x += a.x; acc[r].y += a.y; acc[r].z += a.z; acc[r].w += a.w;
        }
    }
    float4* op = reinterpret_cast<float4*>(out);
    #pragma unroll
    for (int r = 0; r < R; r++) op[selfb + lane + 32 * r] = round_tf32x4(acc[r]);
}

// ---------------------------------------------------------------------------
// Weight transpose + tf32 pre-round: Wt[n][k] = tf32(W[k][n])
// ---------------------------------------------------------------------------
__global__ void transpose_kernel(const float* __restrict__ W,
                                 float* __restrict__ Wt, int K, int Nw)
{
    __shared__ float t[32][33];
    int bx = blockIdx.x * 32;   // n block
    int by = blockIdx.y * 32;   // k block
    int x = threadIdx.x, y = threadIdx.y;
    #pragma unroll
    for (int i = 0; i < 32; i += 8)
        t[y + i][x] = W[(size_t)(by + y + i) * Nw + bx + x];
    __syncthreads();
    #pragma unroll
    for (int i = 0; i < 32; i += 8)
        Wt[(size_t)(bx + y + i) * K + by + x] =
            __uint_as_float(f2tf32(t[x][y + i]));
}

// ---------------------------------------------------------------------------
// tf32 mma.sync GEMM with cp.async double buffering, 1 sync per K-chunk.
//   D[128,128] per block = Apre[128,K] @ Bt[col0..][K]^T
//   AM==0 : A pre-rounded tf32 in memory -> pure cp.async path
//   AM==1 : A = relu(A0*scale+shift), staged via registers (LDG->preop->STS)
//   EM==0 : store acc; accumulate column sum/sumsq into stats
//   EM==1 : store relu(acc+bias)
//   EM==2 : red-add relu(acc+bias) into pooled[batch[m]]
// 256 threads = 8 warps (4x2 of 32x64 warp tiles); BK=32, 2-stage pipeline.
// ---------------------------------------------------------------------------
#define BKP 36
#define CH_U32 (128 * BKP)
#define GEMM_SMEM (4 * CH_U32 * 4)      // 73728 B

template<int AM, int EM>
__global__ void __launch_bounds__(256, 2)
mma_gemm(const int M, const int K,
         const float* __restrict__ A0,
         const float* __restrict__ scale, const float* __restrict__ shift,
         const float* __restrict__ Bt, const float* __restrict__ bias,
         float* __restrict__ C, float* __restrict__ stats,
         float* __restrict__ pooled, const int* __restrict__ batch)
{
    extern __shared__ uint32_t dyn[];
    __shared__ float s_sum[128];
    __shared__ float s_sq[128];
    const uint32_t sbase = smem_u32(dyn);

    const int tid  = threadIdx.x;
    const int lane = tid & 31;
    const int warp = tid >> 5;
    const int grp  = lane >> 2;
    const int tig  = lane & 3;
    const int wm   = (warp >> 1) * 32;
    const int wn   = (warp & 1) * 64;
    const int row0 = blockIdx.x * 128;
    const int col0 = blockIdx.y * 128;

    const int slotRow = tid >> 3;        // 0..31
    const int slotC4  = tid & 7;         // 0..7

    if (EM == 0 && tid < 128) { s_sum[tid] = 0.f; s_sq[tid] = 0.f; }

    float acc[2][8][4];
    #pragma unroll
    for (int mt = 0; mt < 2; mt++)
        #pragma unroll
        for (int nt = 0; nt < 8; nt++)
            #pragma unroll
            for (int q = 0; q < 4; q++) acc[mt][nt][q] = 0.f;

    const int NC = K >> 5;
    float4 aR[4];                         // AM==1 register staging

    auto cpB = [&](int ci, int buf) {
        const int k0 = ci << 5;
        #pragma unroll
        for (int r = 0; r < 4; r++) {
            int row = slotRow + r * 32;
            cp16(sbase + (2 + buf) * (CH_U32 * 4) +
                     (uint32_t)(row * BKP + slotC4 * 4) * 4,
                 Bt + (size_t)(col0 + row) * K + k0 + slotC4 * 4);
        }
    };
    auto cpA = [&](int ci, int buf) {     // AM==0 only (pre-rounded input)
        const int k0 = ci << 5;
        #pragma unroll
        for (int r = 0; r < 4; r++) {
            int row = slotRow + r * 32;
            int gr = row0 + row;
            if (gr < M) {
                cp16(sbase + buf * (CH_U32 * 4) +
                         (uint32_t)(row * BKP + slotC4 * 4) * 4,
                     A0 + (size_t)gr * K + k0 + slotC4 * 4);
            } else {
                *reinterpret_cast<uint4*>(&dyn[buf * CH_U32 + row * BKP + slotC4 * 4]) =
                    make_uint4(0u, 0u, 0u, 0u);
            }
        }
    };
    auto ldA = [&](int ci) {              // AM==1: LDG chunk into registers
        const int k0 = ci << 5;
        #pragma unroll
        for (int r = 0; r < 4; r++) {
            int gr = row0 + slotRow + r * 32;
            aR[r] = (gr < M)
                ? *reinterpret_cast<const float4*>(A0 + (size_t)gr * K + k0 + slotC4 * 4)
                : make_float4(0.f, 0.f, 0.f, 0.f);
        }
    };
    auto stA = [&](int ci, int buf) {     // AM==1: preop + cvt + STS
        const int k0 = ci << 5;
        float4 sc = *reinterpret_cast<const float4*>(scale + k0 + slotC4 * 4);
        float4 sh = *reinterpret_cast<const float4*>(shift + k0 + slotC4 * 4);
        #pragma unroll
        for (int r = 0; r < 4; r++) {
            int row = slotRow + r * 32;
            float4 v = aR[r];
            v.x = fmaxf(fmaf(v.x, sc.x, sh.x), 0.f);
            v.y = fmaxf(fmaf(v.y, sc.y, sh.y), 0.f);
            v.z = fmaxf(fmaf(v.z, sc.z, sh.z), 0.f);
            v.w = fmaxf(fmaf(v.w, sc.w, sh.w), 0.f);
            *reinterpret_cast<uint4*>(&dyn[buf * CH_U32 + row * BKP + slotC4 * 4]) =
                make_uint4(f2tf32(v.x), f2tf32(v.y), f2tf32(v.z), f2tf32(v.w));
        }
    };

    // ---- prologue: chunk 0 ----
    if (AM == 0) cpA(0, 0);
    cpB(0, 0);
    asm volatile("cp.async.commit_group;" ::: "memory");
    if (AM == 1) {
        ldA(0);
        stA(0, 0);
        if (NC > 1) ldA(1);
    }

    // ---- mainloop: one __syncthreads per chunk ----
    for (int i = 0; i < NC; i++) {
        const int buf = i & 1;
        const int nb  = buf ^ 1;
        asm volatile("cp.async.wait_group 0;" ::: "memory");
        __syncthreads();
        if (i + 1 < NC) {
            if (AM == 0) cpA(i + 1, nb);
            else         stA(i + 1, nb);
            cpB(i + 1, nb);
            asm volatile("cp.async.commit_group;" ::: "memory");
            if (AM == 1 && i + 2 < NC) ldA(i + 2);
        }

        const uint32_t* As = &dyn[buf * CH_U32];
        const uint32_t* Bs = &dyn[(2 + buf) * CH_U32];
        #pragma unroll
        for (int ks = 0; ks < 4; ks++) {
            const int kk = ks * 8;
            uint32_t a[2][4];
            #pragma unroll
            for (int mt = 0; mt < 2; mt++) {
                int rbase = (wm + mt * 16 + grp) * BKP + kk;
                a[mt][0] = As[rbase + tig];
                a[mt][1] = As[rbase + 8 * BKP + tig];
                a[mt][2] = As[rbase + tig + 4];
                a[mt][3] = As[rbase + 8 * BKP + tig + 4];
            }
            #pragma unroll
            for (int nt = 0; nt < 8; nt++) {
                int nbase = (wn + nt * 8 + grp) * BKP + kk;
                uint32_t b0 = Bs[nbase + tig];
                uint32_t b1 = Bs[nbase + tig + 4];
                mma_m16n8k8(acc[0][nt], a[0], b0, b1);
                mma_m16n8k8(acc[1][nt], a[1], b0, b1);
            }
        }
        __syncthreads();
    }

    // ---- epilogue ----
    #pragma unroll
    for (int nt = 0; nt < 8; nt++) {
        float cs0 = 0.f, cq0 = 0.f, cs1 = 0.f, cq1 = 0.f;
        #pragma unroll
        for (int mt = 0; mt < 2; mt++) {
            #pragma unroll
            for (int half = 0; half < 2; half++) {
                int gm = row0 + wm + mt * 16 + grp + half * 8;
                if (gm >= M) continue;
                int col = col0 + wn + nt * 8 + 2 * tig;
                float v0 = acc[mt][nt][2 * half];
                float v1 = acc[mt][nt][2 * half + 1];
                if (EM == 0) {
                    cs0 += v0; cq0 += v0 * v0;
                    cs1 += v1; cq1 += v1 * v1;
                    *reinterpret_cast<float2*>(C + (size_t)gm * NCOLS + col) =
                        make_float2(v0, v1);
                } else {
                    v0 = fmaxf(v0 + __ldg(bias + col),     0.f);
                    v1 = fmaxf(v1 + __ldg(bias + col + 1), 0.f);
                    if (EM == 2) {
                        red_add_v2(pooled + (size_t)batch[gm] * NCOLS + col, v0, v1);
                    } else {
                        *reinterpret_cast<float2*>(C + (size_t)gm * NCOLS + col) =
                            make_float2(v0, v1);
                    }
                }
            }
        }
        if (EM == 0) {
            // reduce across the 8 same-column lanes (grp dimension: xor 4,8,16)
            #pragma unroll
            for (int o = 4; o < 32; o <<= 1) {
                cs0 += __shfl_xor_sync(0xffffffffu, cs0, o);
                cq0 += __shfl_xor_sync(0xffffffffu, cq0, o);
                cs1 += __shfl_xor_sync(0xffffffffu, cs1, o);
                cq1 += __shfl_xor_sync(0xffffffffu, cq1, o);
            }
            if (grp == 0) {
                int lc = wn + nt * 8 + 2 * tig;
                atomicAdd(&s_sum[lc],     cs0);
                atomicAdd(&s_sq[lc],      cq0);
                atomicAdd(&s_sum[lc + 1], cs1);
                atomicAdd(&s_sq[lc + 1],  cq1);
            }
        }
    }
    if (EM == 0) {
        __syncthreads();
        if (tid < 128) {
            atomicAdd(&stats[col0 + tid],         s_sum[tid]);
            atomicAdd(&stats[NCOLS + col0 + tid], s_sq[tid]);
        }
    }
}

// ---------------------------------------------------------------------------
// BN stats -> fused scale/shift
// ---------------------------------------------------------------------------
__global__ void bn_finalize(const float* __restrict__ stats,
                            const float* __restrict__ gamma,
                            const float* __restrict__ beta,
                            float* __restrict__ scale,
                            float* __restrict__ shift,
                            float invN)
{
    int c = threadIdx.x;
    float mean = stats[c] * invN;
    float var  = stats[NCOLS + c] * invN - mean * mean;
    float s = gamma[c] * rsqrtf(var + 1e-5f);
    scale[c] = s;
    shift[c] = beta[c] - mean * s;
}

// ---------------------------------------------------------------------------
// Head MLP: out = relu(pooled @ Wl1 + bl1) @ Wl2 + bl2   (64 x 10)
// ---------------------------------------------------------------------------
__global__ void head_kernel(const float* __restrict__ pooled,
                            const float* __restrict__ Wl1,
                            const float* __restrict__ bl1,
                            const float* __restrict__ Wl2,
                            const float* __restrict__ bl2,
                            float* __restrict__ out, int OUTC)
{
    __shared__ float sp[NCOLS];
    __shared__ float sh[NCOLS];
    int g = blockIdx.x, t = threadIdx.x;
    sp[t] = pooled[(size_t)g * NCOLS + t];
    __syncthreads();
    float a = bl1[t];
    for (int k = 0; k < NCOLS; k++)
        a = fmaf(sp[k], Wl1[(size_t)k * NCOLS + t], a);
    sh[t] = fmaxf(a, 0.f);
    __syncthreads();
    if (t < 32 * OUTC) {
        int w = t >> 5, l = t & 31;
        float s = 0.f;
        for (int k = l; k < NCOLS; k += 32)
            s = fmaf(sh[k], Wl2[(size_t)k * OUTC + w], s);
        #pragma unroll
        for (int o = 16; o; o >>= 1)
            s += __shfl_down_sync(0xffffffffu, s, o);
        if (l == 0) out[(size_t)g * OUTC + w] = s + bl2[w];
    }
}

// ---------------------------------------------------------------------------
// Launch
// ---------------------------------------------------------------------------
extern "C" void kernel_launch(void* const* d_in, const int* in_sizes, int n_in,
                              void* d_out, int out_size)
{
    const float* x     = (const float*)d_in[0];
    const void*  ei    = d_in[1];
    const void*  batch = d_in[2];
    const float* W1a = (const float*)d_in[3];
    const float* g1  = (const float*)d_in[5];
    const float* be1 = (const float*)d_in[6];
    const float* W1b = (const float*)d_in[7];
    const float* b1b = (const float*)d_in[8];
    const float* W2a = (const float*)d_in[9];
    const float* g2  = (const float*)d_in[11];
    const float* be2 = (const float*)d_in[12];
    const float* W2b = (const float*)d_in[13];
    const float* b2b = (const float*)d_in[14];
    const float* Wl1 = (const float*)d_in[15];
    const float* bl1 = (const float*)d_in[16];
    const float* Wl2 = (const float*)d_in[17];
    const float* bl2 = (const float*)d_in[18];
    float* out = (float*)d_out;

    const int IN   = 128;
    const int N    = in_sizes[0] / IN;        // 50000
    const int E    = in_sizes[1] / 2;         // 800000
    const int OUTC = in_sizes[18];            // 10
    const int G    = out_size / OUTC;         // 64

    float *comb, *z, *h1, *stats, *scale, *shift, *pooled;
    float *Wt1a, *Wt1b, *Wt2a, *Wt2b;
    int *batchI, *offI, *curI, *bsumI;
    cudaGetSymbolAddress((void**)&comb,   g_agg);
    cudaGetSymbolAddress((void**)&z,      g_z);
    cudaGetSymbolAddress((void**)&h1,     g_h1);
    cudaGetSymbolAddress((void**)&stats,  g_stats);
    cudaGetSymbolAddress((void**)&scale,  g_scale);
    cudaGetSymbolAddress((void**)&shift,  g_shift);
    cudaGetSymbolAddress((void**)&pooled, g_pooled);
    cudaGetSymbolAddress((void**)&batchI, g_batch);
    cudaGetSymbolAddress((void**)&offI,   g_off);
    cudaGetSymbolAddress((void**)&curI,   g_cur);
    cudaGetSymbolAddress((void**)&bsumI,  g_bsum);
    cudaGetSymbolAddress((void**)&Wt1a,   g_Wt1a);
    cudaGetSymbolAddress((void**)&Wt1b,   g_Wt1b);
    cudaGetSymbolAddress((void**)&Wt2a,   g_Wt2a);
    cudaGetSymbolAddress((void**)&Wt2b,   g_Wt2b);

    cudaFuncSetAttribute(mma_gemm<0, 0>, cudaFuncAttributeMaxDynamicSharedMemorySize, GEMM_SMEM);
    cudaFuncSetAttribute(mma_gemm<1, 1>, cudaFuncAttributeMaxDynamicSharedMemorySize, GEMM_SMEM);
    cudaFuncSetAttribute(mma_gemm<1, 2>, cudaFuncAttributeMaxDynamicSharedMemorySize, GEMM_SMEM);

    // ---- canonicalize indices; build CSR; transpose weights (tf32) ----
    detect_kernel<<<1, 128>>>((const unsigned*)ei);
    convert_kernel<<<(E + 255) / 256, 256>>>(ei, batch, E, N);
    cudaMemsetAsync(curI, 0, (size_t)N * sizeof(int));
    hist_kernel<<<(E + 255) / 256, 256>>>(E);
    const int nb = (N + 1023) / 1024;         // 49
    scan_block<<<nb, 1024>>>(curI, offI, bsumI, N);
    scan_tops<<<1, 64>>>(bsumI, nb);
    scan_add<<<nb, 1024>>>(offI, bsumI, N, E);
    copy_kernel<<<(N + 255) / 256, 256>>>(offI, curI, N);
    reorder_kernel<<<(E + 255) / 256, 256>>>(E);
    {
        dim3 blk(32, 8);
        transpose_kernel<<<dim3(16, IN / 32),    blk>>>(W1a, Wt1a, IN,    NCOLS);
        transpose_kernel<<<dim3(16, NCOLS / 32), blk>>>(W1b, Wt1b, NCOLS, NCOLS);
        transpose_kernel<<<dim3(16, NCOLS / 32), blk>>>(W2a, Wt2a, NCOLS, NCOLS);
        transpose_kernel<<<dim3(16, NCOLS / 32), blk>>>(W2b, Wt2b, NCOLS, NCOLS);
    }

    const dim3 ggrid((N + 127) / 128, 4);
    const int gatherBlocks = (N * 32 + 255) / 256;

    // ---------------- Layer 1 ----------------
    cudaMemsetAsync(stats, 0, 2 * NCOLS * sizeof(float));
    gather_csr<1><<<gatherBlocks, 256>>>(x, comb, N);
    mma_gemm<0, 0><<<ggrid, 256, GEMM_SMEM>>>(N, IN, comb, nullptr, nullptr,
                                              Wt1a, nullptr, z, stats, nullptr, nullptr);
    bn_finalize<<<1, NCOLS>>>(stats, g1, be1, scale, shift, 1.0f / N);
    mma_gemm<1, 1><<<ggrid, 256, GEMM_SMEM>>>(N, NCOLS, z, scale, shift,
                                              Wt1b, b1b, h1, nullptr, nullptr, nullptr);

    // ---------------- Layer 2 ----------------
    cudaMemsetAsync(stats, 0, 2 * NCOLS * sizeof(float));
    gather_csr<4><<<gatherBlocks, 256>>>(h1, comb, N);
    mma_gemm<0, 0><<<ggrid, 256, GEMM_SMEM>>>(N, NCOLS, comb, nullptr, nullptr,
                                              Wt2a, nullptr, z, stats, nullptr, nullptr);
    bn_finalize<<<1, NCOLS>>>(stats, g2, be2, scale, shift, 1.0f / N);
    cudaMemsetAsync(pooled, 0, (size_t)G * NCOLS * sizeof(float));
    mma_gemm<1, 2><<<ggrid, 256, GEMM_SMEM>>>(N, NCOLS, z, scale, shift,
                                              Wt2b, b2b, nullptr, nullptr, pooled, batchI);

    // ---------------- Head ----------------
    head_kernel<<<G, NCOLS>>>(pooled, Wl1, bl1, Wl2, bl2, out, OUTC);
}